// round 1
// baseline (speedup 1.0000x reference)
#include <cuda_runtime.h>

// QuantizationLayer: out[b, n*3 + i] = bit (2-i) of round_half_even(x[b,n]*8 - 0.5)
// x: [65536, 512] fp32 in [0,1) -> q in [0,7] -> 3 bits MSB-first as fp32 0/1.
//
// Streaming kernel: 1 thread = 4 input floats (1x LDG.128) -> 12 output floats
// (3x STG.128). 512 MB total HBM traffic; fully DRAM-bound.

__global__ void __launch_bounds__(256) quant_bits_kernel(
    const float4* __restrict__ in, float4* __restrict__ out, int n4)
{
    int t = blockIdx.x * blockDim.x + threadIdx.x;
    if (t >= n4) return;

    float4 v = in[t];

    // q = round-half-even(x*8 - 0.5); both ops exact in fp32, F2I.RN ties-to-even.
    int q0 = __float2int_rn(v.x * 8.0f - 0.5f);
    int q1 = __float2int_rn(v.y * 8.0f - 0.5f);
    int q2 = __float2int_rn(v.z * 8.0f - 0.5f);
    int q3 = __float2int_rn(v.w * 8.0f - 0.5f);

    float4 o0, o1, o2;
    // element 0 -> bits 0..2, element 1 -> bits 3..5, etc. MSB first per element.
    o0.x = (float)((q0 >> 2) & 1);
    o0.y = (float)((q0 >> 1) & 1);
    o0.z = (float)( q0       & 1);
    o0.w = (float)((q1 >> 2) & 1);
    o1.x = (float)((q1 >> 1) & 1);
    o1.y = (float)( q1       & 1);
    o1.z = (float)((q2 >> 2) & 1);
    o1.w = (float)((q2 >> 1) & 1);
    o2.x = (float)( q2       & 1);
    o2.y = (float)((q3 >> 2) & 1);
    o2.z = (float)((q3 >> 1) & 1);
    o2.w = (float)( q3       & 1);

    int ob = 3 * t;
    out[ob + 0] = o0;
    out[ob + 1] = o1;
    out[ob + 2] = o2;
}

extern "C" void kernel_launch(void* const* d_in, const int* in_sizes, int n_in,
                              void* d_out, int out_size)
{
    const float4* in = (const float4*)d_in[0];
    float4* out = (float4*)d_out;
    int n = in_sizes[0];          // 33,554,432 elements
    int n4 = n / 4;               // 8,388,608 float4 loads, no tail (n % 4 == 0)

    int threads = 256;
    int blocks = (n4 + threads - 1) / threads;
    quant_bits_kernel<<<blocks, threads>>>(in, out, n4);
}

// round 2
// speedup vs baseline: 1.1553x; 1.1553x over previous
#include <cuda_runtime.h>

// QuantizationLayer: out[b, 3n+i] = bit (2-i) of round_half_even(x[b,n]*8 - 0.5)
// x: [65536, 512] fp32 -> q in [0,7] -> 3 bits MSB-first as fp32 0/1.
//
// R2: fix store coalescing. Each thread quantizes 4 input floats (1 LDG.128)
// into 12 output floats, stages them in shared memory, then each warp writes
// its 96 contiguous float4s coalesced (3 STG.128 per lane at +0/+32/+64).
// Smem strides are bank-conflict-free in both phases.

__global__ void __launch_bounds__(256) quant_bits_kernel(
    const float4* __restrict__ in, float4* __restrict__ out, int n4)
{
    __shared__ float4 stage[8][96];   // 8 warps * 96 float4 = 12 KB

    int t = blockIdx.x * blockDim.x + threadIdx.x;
    if (t >= n4) return;              // n4 % 256 == 0: whole warps exit together

    int warp = threadIdx.x >> 5;
    int lane = threadIdx.x & 31;

    float4 v = in[t];

    // round-half-even(x*8 - 0.5): both fp ops exact, F2I.RN ties-to-even.
    int q0 = __float2int_rn(v.x * 8.0f - 0.5f);
    int q1 = __float2int_rn(v.y * 8.0f - 0.5f);
    int q2 = __float2int_rn(v.z * 8.0f - 0.5f);
    int q3 = __float2int_rn(v.w * 8.0f - 0.5f);

    float4 o0, o1, o2;
    o0.x = (float)((q0 >> 2) & 1);
    o0.y = (float)((q0 >> 1) & 1);
    o0.z = (float)( q0       & 1);
    o0.w = (float)((q1 >> 2) & 1);
    o1.x = (float)((q1 >> 1) & 1);
    o1.y = (float)( q1       & 1);
    o1.z = (float)((q2 >> 2) & 1);
    o1.w = (float)((q2 >> 1) & 1);
    o2.x = (float)( q2       & 1);
    o2.y = (float)((q3 >> 2) & 1);
    o2.z = (float)((q3 >> 1) & 1);
    o2.w = (float)( q3       & 1);

    // Stage: byte stride 48/lane -> conflict-free STS.128 (banks 12l mod 32).
    stage[warp][3 * lane + 0] = o0;
    stage[warp][3 * lane + 1] = o1;
    stage[warp][3 * lane + 2] = o2;
    __syncwarp();

    // Coalesced writeback: global warp id * 96 float4s, lanes contiguous.
    int base = (t >> 5) * 96;
    out[base + lane     ] = stage[warp][lane     ];
    out[base + lane + 32] = stage[warp][lane + 32];
    out[base + lane + 64] = stage[warp][lane + 64];
}

extern "C" void kernel_launch(void* const* d_in, const int* in_sizes, int n_in,
                              void* d_out, int out_size)
{
    const float4* in = (const float4*)d_in[0];
    float4* out = (float4*)d_out;
    int n = in_sizes[0];          // 33,554,432 elements
    int n4 = n / 4;               // 8,388,608 float4 loads

    int threads = 256;
    int blocks = (n4 + threads - 1) / threads;
    quant_bits_kernel<<<blocks, threads>>>(in, out, n4);
}